// round 1
// baseline (speedup 1.0000x reference)
#include <cuda_runtime.h>
#include <math.h>

#define NN 50000
#define EE 800000
#define BB 50
#define GN_EPS 1e-5f

// ---------------- scratch (static device memory; no allocations) ----------------
__device__ float g_f0[(size_t)NN * 512];
__device__ float g_f1[(size_t)NN * 512];
__device__ float g_tx1[(size_t)NN * 512];
__device__ float g_tx2[(size_t)NN * 512];
__device__ int   g_deg[NN];
__device__ float g_dinv[NN];
__device__ int   g_off[NN + 1];
__device__ int   g_fill[NN];
__device__ int   g_srcs[EE];
__device__ float g_ws[EE];
__device__ int   g_ptr[BB + 1];
__device__ float g_cnt[BB];
__device__ float g_pool[BB * 128];

static inline int cdiv(int a, int b) { return (a + b - 1) / b; }

// ---------------- setup kernels ----------------
__global__ void k_zero_deg() {
    int i = blockIdx.x * blockDim.x + threadIdx.x;
    if (i < NN) g_deg[i] = 0;
}

__global__ void k_deg(const int* __restrict__ dst) {
    int e = blockIdx.x * blockDim.x + threadIdx.x;
    if (e < EE) atomicAdd(&g_deg[dst[e]], 1);
}

__global__ void k_dinv() {
    int n = blockIdx.x * blockDim.x + threadIdx.x;
    if (n < NN) {
        int d = g_deg[n];
        g_dinv[n] = (d > 0) ? rsqrtf((float)d) : 0.0f;
    }
}

// single-block exclusive scan of g_deg -> g_off (and copy to g_fill)
__global__ void k_scan() {
    __shared__ int part[1024];
    int tid = threadIdx.x;
    const int CH = (NN + 1023) / 1024;
    int s = tid * CH;
    int e = min(s + CH, NN);
    int sum = 0;
    for (int i = s; i < e; i++) sum += g_deg[i];
    part[tid] = sum;
    __syncthreads();
    for (int off = 1; off < 1024; off <<= 1) {
        int v = 0;
        if (tid >= off) v = part[tid - off];
        __syncthreads();
        part[tid] += v;
        __syncthreads();
    }
    int base = (tid == 0) ? 0 : part[tid - 1];
    for (int i = s; i < e; i++) {
        g_off[i] = base;
        g_fill[i] = base;
        base += g_deg[i];
    }
    if (tid == 1023) g_off[NN] = part[1023];
}

__global__ void k_fill(const int* __restrict__ src, const int* __restrict__ dst) {
    int e = blockIdx.x * blockDim.x + threadIdx.x;
    if (e < EE) {
        int d = dst[e];
        int s = src[e];
        int pos = atomicAdd(&g_fill[d], 1);
        g_srcs[pos] = s;
        g_ws[pos] = -g_dinv[s] * g_dinv[d];
    }
}

__global__ void k_ptr(const int* __restrict__ batch) {
    int n = blockIdx.x * blockDim.x + threadIdx.x;
    if (n >= NN) return;
    int b = batch[n];
    if (n == 0) {
        for (int bb = 0; bb <= b; bb++) g_ptr[bb] = 0;
    } else {
        int pb = batch[n - 1];
        for (int bb = pb + 1; bb <= b; bb++) g_ptr[bb] = n;
    }
    if (n == NN - 1) {
        for (int bb = b + 1; bb <= BB; bb++) g_ptr[bb] = NN;
    }
}

__global__ void k_cnt() {
    int b = threadIdx.x;
    if (b < BB) {
        int c = g_ptr[b + 1] - g_ptr[b];
        g_cnt[b] = (c > 0) ? (float)c : 1.0f;
    }
}

// ---------------- propagation: out[n] = scale*sum_e(w*h[src]) + beta*base[n] ----------------
template <int CPT>
__global__ void k_prop(const float* __restrict__ h, const float* __restrict__ base,
                       float scale, float beta, float* __restrict__ out, int cin) {
    int n = blockIdx.x;
    int s = g_off[n];
    int e = g_off[n + 1];
    int c = threadIdx.x;
    float acc[CPT];
#pragma unroll
    for (int i = 0; i < CPT; i++) acc[i] = 0.0f;
    for (int ed = s; ed < e; ed++) {
        int src = __ldg(&g_srcs[ed]);
        float w = __ldg(&g_ws[ed]);
        const float* hp = h + (size_t)src * cin + c;
#pragma unroll
        for (int i = 0; i < CPT; i++) acc[i] += w * __ldg(hp + i * 128);
    }
    size_t o = (size_t)n * cin + c;
#pragma unroll
    for (int i = 0; i < CPT; i++) {
        float v = scale * acc[i];
        if (base) v += beta * base[o + i * 128];
        out[o + i * 128] = v;
    }
}

// ---------------- GEMM: C = A0@W[0] + A1@W[1] + A2@W[2] + bias ----------------
// W is [3, cin, cout] contiguous. 128x128 tile, BK=8, 256 threads, 8x8 microtile.
__global__ void k_gemm3(const float* __restrict__ A0, const float* __restrict__ A1,
                        const float* __restrict__ A2, const float* __restrict__ W,
                        const float* __restrict__ bias, float* __restrict__ C,
                        int M, int cin, int cout) {
    __shared__ float As[8][128];
    __shared__ float Bs[8][128];
    int m0 = blockIdx.x * 128;
    int n0 = blockIdx.y * 128;
    int tid = threadIdx.x;
    int tr = tid >> 4;      // 0..15
    int tc = tid & 15;      // 0..15
    float acc[8][8];
#pragma unroll
    for (int i = 0; i < 8; i++)
#pragma unroll
        for (int j = 0; j < 8; j++) acc[i][j] = 0.0f;

    int K = 3 * cin;
    int arow = tid >> 1;
    int akq = (tid & 1) * 4;
    int brow = tid >> 5;
    int bcol = (tid & 31) * 4;

    for (int kk = 0; kk < K; kk += 8) {
        int sel = kk / cin;
        const float* A = (sel == 0) ? A0 : ((sel == 1) ? A1 : A2);
        int kloc = kk - sel * cin;

        float4 av = make_float4(0.f, 0.f, 0.f, 0.f);
        int gr = m0 + arow;
        if (gr < M) av = *(const float4*)(A + (size_t)gr * cin + kloc + akq);
        As[akq + 0][arow] = av.x;
        As[akq + 1][arow] = av.y;
        As[akq + 2][arow] = av.z;
        As[akq + 3][arow] = av.w;

        float4 bv = *(const float4*)(W + (size_t)(kk + brow) * cout + n0 + bcol);
        *(float4*)&Bs[brow][bcol] = bv;
        __syncthreads();

#pragma unroll
        for (int k = 0; k < 8; k++) {
            float a[8], b[8];
#pragma unroll
            for (int i = 0; i < 8; i++) a[i] = As[k][tr * 8 + i];
#pragma unroll
            for (int j = 0; j < 8; j++) b[j] = Bs[k][tc * 8 + j];
#pragma unroll
            for (int i = 0; i < 8; i++)
#pragma unroll
                for (int j = 0; j < 8; j++) acc[i][j] += a[i] * b[j];
        }
        __syncthreads();
    }

#pragma unroll
    for (int i = 0; i < 8; i++) {
        int gr = m0 + tr * 8 + i;
        if (gr >= M) break;
#pragma unroll
        for (int j = 0; j < 8; j++) {
            int gc = n0 + tc * 8 + j;
            C[(size_t)gr * cout + gc] = acc[i][j] + bias[gc];
        }
    }
}

// ---------------- GraphNorm + leaky relu, in-place ----------------
__global__ void k_graphnorm(float* __restrict__ X, const float* __restrict__ w,
                            const float* __restrict__ b, const float* __restrict__ ms,
                            int cout) {
    int bg = blockIdx.x;
    int c = blockIdx.y * blockDim.x + threadIdx.x;
    if (c >= cout) return;
    int s = g_ptr[bg];
    int e = g_ptr[bg + 1];
    float invc = 1.0f / g_cnt[bg];
    float sum = 0.0f;
    for (int n = s; n < e; n++) sum += X[(size_t)n * cout + c];
    float mean = ms[c] * (sum * invc);
    float ss = 0.0f;
    for (int n = s; n < e; n++) {
        float d = X[(size_t)n * cout + c] - mean;
        ss += d * d;
    }
    float inv = rsqrtf(ss * invc + GN_EPS);
    float ww = w[c] * inv;
    float bb = b[c];
    for (int n = s; n < e; n++) {
        float d = X[(size_t)n * cout + c] - mean;
        float v = ww * d + bb;
        X[(size_t)n * cout + c] = (v >= 0.f) ? v : 0.2f * v;
    }
}

// ---------------- residual + mean pool ----------------
__global__ void k_pool(const float* __restrict__ h, const float* __restrict__ x) {
    int bg = blockIdx.x;
    int c = threadIdx.x;  // 128
    int s = g_ptr[bg];
    int e = g_ptr[bg + 1];
    float sum = 0.0f;
    for (int n = s; n < e; n++)
        sum += h[(size_t)n * 128 + c] + x[(size_t)n * 128 + c];
    g_pool[bg * 128 + c] = sum / g_cnt[bg];
}

// ---------------- MLP head ----------------
__global__ void k_head(const float* __restrict__ W1, const float* __restrict__ b1,
                       const float* __restrict__ W2, const float* __restrict__ b2,
                       float* __restrict__ out) {
    int bg = blockIdx.x;
    __shared__ float hid[64];
    int j = threadIdx.x;  // 64
    float s = b1[j];
    for (int i = 0; i < 128; i++) s += g_pool[bg * 128 + i] * W1[i * 64 + j];
    hid[j] = tanhf(s);
    __syncthreads();
    if (j < 10) {
        float o = b2[j];
        for (int i = 0; i < 64; i++) o += hid[i] * W2[i * 10 + j];
        out[bg * 10 + j] = o;
    }
}

// ---------------- host orchestration ----------------
static void launch_prop(const float* h, const float* base, float scale, float beta,
                        float* out, int cin) {
    switch (cin / 128) {
        case 1: k_prop<1><<<NN, 128>>>(h, base, scale, beta, out, cin); break;
        case 2: k_prop<2><<<NN, 128>>>(h, base, scale, beta, out, cin); break;
        default: k_prop<4><<<NN, 128>>>(h, base, scale, beta, out, cin); break;
    }
}

static void run_layer(const float* h, float* out, float* tx1, float* tx2,
                      int cin, int cout, void* const* d_in, int base_idx) {
    launch_prop(h, nullptr, 1.0f, 0.0f, tx1, cin);
    launch_prop(tx1, h, 2.0f, -1.0f, tx2, cin);
    dim3 gg(cdiv(NN, 128), cout / 128);
    k_gemm3<<<gg, 256>>>(h, tx1, tx2,
                         (const float*)d_in[base_idx], (const float*)d_in[base_idx + 1],
                         out, NN, cin, cout);
    dim3 gn(BB, cdiv(cout, 128));
    k_graphnorm<<<gn, 128>>>(out,
                             (const float*)d_in[base_idx + 2],
                             (const float*)d_in[base_idx + 3],
                             (const float*)d_in[base_idx + 4], cout);
}

extern "C" void kernel_launch(void* const* d_in, const int* in_sizes, int n_in,
                              void* d_out, int out_size) {
    const float* x = (const float*)d_in[0];
    const int* ei = (const int*)d_in[1];
    const int* src = ei;
    const int* dst = ei + EE;
    const int* batch = (const int*)d_in[2];

    float *f0, *f1, *tx1, *tx2;
    cudaGetSymbolAddress((void**)&f0, g_f0);
    cudaGetSymbolAddress((void**)&f1, g_f1);
    cudaGetSymbolAddress((void**)&tx1, g_tx1);
    cudaGetSymbolAddress((void**)&tx2, g_tx2);

    // ---- setup: degrees, CSR, graph segments ----
    k_zero_deg<<<cdiv(NN, 256), 256>>>();
    k_deg<<<cdiv(EE, 256), 256>>>(dst);
    k_dinv<<<cdiv(NN, 256), 256>>>();
    k_scan<<<1, 1024>>>();
    k_fill<<<cdiv(EE, 256), 256>>>(src, dst);
    k_ptr<<<cdiv(NN, 256), 256>>>(batch);
    k_cnt<<<1, 64>>>();

    // ---- 4 Cheb layers ----
    run_layer(x,  f0, tx1, tx2, 128, 256, d_in, 3);
    run_layer(f0, f1, tx1, tx2, 256, 512, d_in, 8);
    run_layer(f1, f0, tx1, tx2, 512, 256, d_in, 13);
    run_layer(f0, f1, tx1, tx2, 256, 128, d_in, 18);

    // ---- residual + pool + head ----
    k_pool<<<BB, 128>>>(f1, x);
    k_head<<<BB, 64>>>((const float*)d_in[23], (const float*)d_in[24],
                       (const float*)d_in[25], (const float*)d_in[26],
                       (float*)d_out);
}

// round 3
// speedup vs baseline: 1.4072x; 1.4072x over previous
#include <cuda_runtime.h>
#include <cuda_bf16.h>
#include <math.h>
#include <cstdint>

#define NN 50000
#define EE 800000
#define BB 50
#define GN_EPS 1e-5f
#define MPAD 50048   // 391 * 128

// ---------------- scratch (static device memory; no allocations) ----------------
__device__ float g_f0[(size_t)NN * 512];
__device__ float g_f1[(size_t)NN * 512];
__device__ float g_tx1[(size_t)NN * 512];
__device__ float g_tx2[(size_t)NN * 512];
__device__ __nv_bfloat16 g_abf[(size_t)MPAD * 3072];   // [rows, 6*cin] = [Ah | Al]; pad rows stay 0
__device__ __nv_bfloat16 g_wbf[(size_t)512 * 4608];    // [cout, 9*cin] = [Wh ; Wh ; Wl] (n-major)
__device__ int   g_deg[NN];
__device__ float g_dinv[NN];
__device__ int   g_off[NN + 1];
__device__ int   g_fill[NN];
__device__ int   g_srcs[EE];
__device__ float g_ws[EE];
__device__ int   g_ptr[BB + 1];
__device__ float g_cnt[BB];
__device__ float g_pool[BB * 128];

static inline int cdiv(int a, int b) { return (a + b - 1) / b; }

// ---------------- PTX helpers ----------------
__device__ __forceinline__ uint32_t smem_u32(const void* p) {
    uint32_t a;
    asm("{ .reg .u64 t; cvta.to.shared.u64 t, %1; cvt.u32.u64 %0, t; }" : "=r"(a) : "l"(p));
    return a;
}

__device__ __forceinline__ void cp_async16(uint32_t dst, const void* src) {
    asm volatile("cp.async.cg.shared.global [%0], [%1], 16;\n" :: "r"(dst), "l"(src));
}
#define CP_COMMIT() asm volatile("cp.async.commit_group;\n" ::: "memory")
#define CP_WAIT(n)  asm volatile("cp.async.wait_group %0;\n" :: "n"(n) : "memory")

__device__ __forceinline__ void mma_bf16(float* c, uint32_t a0, uint32_t a1, uint32_t a2,
                                         uint32_t a3, uint32_t b0, uint32_t b1) {
    asm volatile(
        "mma.sync.aligned.m16n8k16.row.col.f32.bf16.bf16.f32 "
        "{%0,%1,%2,%3}, {%4,%5,%6,%7}, {%8,%9}, {%0,%1,%2,%3};"
        : "+f"(c[0]), "+f"(c[1]), "+f"(c[2]), "+f"(c[3])
        : "r"(a0), "r"(a1), "r"(a2), "r"(a3), "r"(b0), "r"(b1));
}

// ---------------- setup kernels ----------------
__global__ void k_zero_deg() {
    int i = blockIdx.x * blockDim.x + threadIdx.x;
    if (i < NN) g_deg[i] = 0;
}

__global__ void k_deg(const int* __restrict__ dst) {
    int e = blockIdx.x * blockDim.x + threadIdx.x;
    if (e < EE) atomicAdd(&g_deg[dst[e]], 1);
}

__global__ void k_dinv() {
    int n = blockIdx.x * blockDim.x + threadIdx.x;
    if (n < NN) {
        int d = g_deg[n];
        g_dinv[n] = (d > 0) ? rsqrtf((float)d) : 0.0f;
    }
}

__global__ void k_scan() {
    __shared__ int part[1024];
    int tid = threadIdx.x;
    const int CH = (NN + 1023) / 1024;
    int s = tid * CH;
    int e = min(s + CH, NN);
    int sum = 0;
    for (int i = s; i < e; i++) sum += g_deg[i];
    part[tid] = sum;
    __syncthreads();
    for (int off = 1; off < 1024; off <<= 1) {
        int v = 0;
        if (tid >= off) v = part[tid - off];
        __syncthreads();
        part[tid] += v;
        __syncthreads();
    }
    int base = (tid == 0) ? 0 : part[tid - 1];
    for (int i = s; i < e; i++) {
        g_off[i] = base;
        g_fill[i] = base;
        base += g_deg[i];
    }
    if (tid == 1023) g_off[NN] = part[1023];
}

__global__ void k_fill(const int* __restrict__ src, const int* __restrict__ dst) {
    int e = blockIdx.x * blockDim.x + threadIdx.x;
    if (e < EE) {
        int d = dst[e];
        int s = src[e];
        int pos = atomicAdd(&g_fill[d], 1);
        g_srcs[pos] = s;
        g_ws[pos] = -g_dinv[s] * g_dinv[d];
    }
}

__global__ void k_ptr(const int* __restrict__ batch) {
    int n = blockIdx.x * blockDim.x + threadIdx.x;
    if (n >= NN) return;
    int b = batch[n];
    if (n == 0) {
        for (int bb = 0; bb <= b; bb++) g_ptr[bb] = 0;
    } else {
        int pb = batch[n - 1];
        for (int bb = pb + 1; bb <= b; bb++) g_ptr[bb] = n;
    }
    if (n == NN - 1) {
        for (int bb = b + 1; bb <= BB; bb++) g_ptr[bb] = NN;
    }
}

__global__ void k_cnt() {
    int b = threadIdx.x;
    if (b < BB) {
        int c = g_ptr[b + 1] - g_ptr[b];
        g_cnt[b] = (c > 0) ? (float)c : 1.0f;
    }
}

// ---------------- propagation: out[n] = scale*sum_e(w*h[src]) + beta*base[n] ----------------
template <int CPT>
__global__ void k_prop(const float* __restrict__ h, const float* __restrict__ base,
                       float scale, float beta, float* __restrict__ out, int cin) {
    int n = blockIdx.x;
    int s = g_off[n];
    int e = g_off[n + 1];
    int c = threadIdx.x;
    float acc[CPT];
#pragma unroll
    for (int i = 0; i < CPT; i++) acc[i] = 0.0f;
    for (int ed = s; ed < e; ed++) {
        int src = __ldg(&g_srcs[ed]);
        float w = __ldg(&g_ws[ed]);
        const float* hp = h + (size_t)src * cin + c;
#pragma unroll
        for (int i = 0; i < CPT; i++) acc[i] += w * __ldg(hp + i * 128);
    }
    size_t o = (size_t)n * cin + c;
#pragma unroll
    for (int i = 0; i < CPT; i++) {
        float v = scale * acc[i];
        if (base) v += beta * base[o + i * 128];
        out[o + i * 128] = v;
    }
}

// ---------------- convert activations: [h|tx1|tx2] fp32 -> [Ah | Al] bf16 split ----------------
__global__ void k_convA(const float* __restrict__ h, const float* __restrict__ t1,
                        const float* __restrict__ t2, int cin) {
    int idx = blockIdx.x * blockDim.x + threadIdx.x;
    int total = NN * cin;
    if (idx >= total) return;
    int n = idx / cin;
    int c = idx - n * cin;
    size_t ob = (size_t)n * (6 * cin);
    float v0 = h[idx], v1 = t1[idx], v2 = t2[idx];
    __nv_bfloat16 h0 = __float2bfloat16_rn(v0);
    __nv_bfloat16 h1 = __float2bfloat16_rn(v1);
    __nv_bfloat16 h2 = __float2bfloat16_rn(v2);
    g_abf[ob + c] = h0;
    g_abf[ob + cin + c] = h1;
    g_abf[ob + 2 * cin + c] = h2;
    g_abf[ob + 3 * cin + c] = __float2bfloat16_rn(v0 - __bfloat162float(h0));
    g_abf[ob + 4 * cin + c] = __float2bfloat16_rn(v1 - __bfloat162float(h1));
    g_abf[ob + 5 * cin + c] = __float2bfloat16_rn(v2 - __bfloat162float(h2));
}

// ---------------- convert weights: W[3cin,cout] -> g_wbf[cout, 9cin] = [Wh;Wh;Wl]^T ----------------
__global__ void k_convW(const float* __restrict__ W, int cin, int cout) {
    int K9 = 9 * cin;
    int idx = blockIdx.x * blockDim.x + threadIdx.x;
    if (idx >= cout * K9) return;
    int n = idx / K9;
    int R = idx - n * K9;
    int src = R;
    if (src >= 6 * cin) src -= 6 * cin;
    else if (src >= 3 * cin) src -= 3 * cin;
    float w = W[(size_t)src * cout + n];
    __nv_bfloat16 hi = __float2bfloat16_rn(w);
    __nv_bfloat16 v = (R < 6 * cin) ? hi : __float2bfloat16_rn(w - __bfloat162float(hi));
    g_wbf[(size_t)n * K9 + R] = v;
}

// ---------------- tensor-core GEMM via mma.sync (HMMA): C = A @ W^T + bias ----------------
// A = g_abf [MPAD, 6cin] (virtual K9=9cin), B = g_wbf [cout, K9] (n-major => col-major B).
// 128x128 tile, BK=32 bf16, 256 threads (8 warps 2x4), warp tile 64x32, double-buffered cp.async.
#define BM 128
#define BN 128
#define BK 32
#define ASTR 48   // smem row stride in bf16 (96 bytes: 16B-aligned, spreads banks)

__global__ void __launch_bounds__(256)
k_gemm_mma(const float* __restrict__ bias, float* __restrict__ C, int cin, int cout) {
    __shared__ __align__(16) __nv_bfloat16 As[2][BM * ASTR];
    __shared__ __align__(16) __nv_bfloat16 Bs[2][BN * ASTR];
    int tid = threadIdx.x;
    int lane = tid & 31;
    int wid = tid >> 5;
    int wm = wid >> 2;   // 0..1 -> 64 rows each
    int wn = wid & 3;    // 0..3 -> 32 cols each
    int m0 = blockIdx.x * BM;
    int n0 = blockIdx.y * BN;
    int K9 = 9 * cin;
    int sA = 6 * cin;
    int nch = K9 / BK;

    float c[4][4][4] = {};

    int lrow = tid >> 2;          // 0..63
    int lcol = (tid & 3) * 8;     // bf16 offset within 32-col chunk (16B)
    uint32_t sa = smem_u32(As);
    uint32_t sb = smem_u32(Bs);
    uint32_t dstA = sa + (uint32_t)(lrow * ASTR + lcol) * 2;
    uint32_t dstB = sb + (uint32_t)(lrow * ASTR + lcol) * 2;
    const uint32_t bufsz = (uint32_t)BM * ASTR * 2;

    // fragment addresses (within a buffer)
    int qr = lane >> 2;           // 0..7
    int qc = (lane & 3) * 2;      // 0,2,4,6

    // prefetch chunk 0
    {
        int kg = 0;
        const __nv_bfloat16* ag = g_abf + (size_t)(m0 + lrow) * sA + kg + lcol;
        const __nv_bfloat16* bg = g_wbf + (size_t)(n0 + lrow) * K9 + kg + lcol;
        cp_async16(dstA, ag);
        cp_async16(dstA + 64u * ASTR * 2, ag + (size_t)64 * sA);
        cp_async16(dstB, bg);
        cp_async16(dstB + 64u * ASTR * 2, bg + (size_t)64 * K9);
        CP_COMMIT();
    }

    for (int ch = 0; ch < nch; ch++) {
        int buf = ch & 1;
        if (ch + 1 < nch) {
            int kg = (ch + 1) * BK;
            int acol = (kg < sA) ? kg : kg - sA;
            const __nv_bfloat16* ag = g_abf + (size_t)(m0 + lrow) * sA + acol + lcol;
            const __nv_bfloat16* bg = g_wbf + (size_t)(n0 + lrow) * K9 + kg + lcol;
            uint32_t da = dstA + (buf ^ 1) * bufsz;
            uint32_t db = dstB + (buf ^ 1) * bufsz;
            cp_async16(da, ag);
            cp_async16(da + 64u * ASTR * 2, ag + (size_t)64 * sA);
            cp_async16(db, bg);
            cp_async16(db + 64u * ASTR * 2, bg + (size_t)64 * K9);
            CP_COMMIT();
            CP_WAIT(1);
        } else {
            CP_WAIT(0);
        }
        __syncthreads();

        const __nv_bfloat16* Ab = As[buf];
        const __nv_bfloat16* Bb = Bs[buf];
#pragma unroll
        for (int ks = 0; ks < 2; ks++) {
            int kof = ks * 16 + qc;
            uint32_t a[4][4];
#pragma unroll
            for (int mi = 0; mi < 4; mi++) {
                const __nv_bfloat16* p = Ab + (wm * 64 + mi * 16 + qr) * ASTR + kof;
                a[mi][0] = *(const uint32_t*)(p);
                a[mi][1] = *(const uint32_t*)(p + 8 * ASTR);
                a[mi][2] = *(const uint32_t*)(p + 8);
                a[mi][3] = *(const uint32_t*)(p + 8 * ASTR + 8);
            }
            uint32_t b[4][2];
#pragma unroll
            for (int ni = 0; ni < 4; ni++) {
                const __nv_bfloat16* p = Bb + (wn * 32 + ni * 8 + qr) * ASTR + kof;
                b[ni][0] = *(const uint32_t*)(p);
                b[ni][1] = *(const uint32_t*)(p + 8);
            }
#pragma unroll
            for (int mi = 0; mi < 4; mi++)
#pragma unroll
                for (int ni = 0; ni < 4; ni++)
                    mma_bf16(c[mi][ni], a[mi][0], a[mi][1], a[mi][2], a[mi][3],
                             b[ni][0], b[ni][1]);
        }
        __syncthreads();
    }

    // epilogue: direct stores (float2) + bias
    float bv0[4], bv1[4];
#pragma unroll
    for (int ni = 0; ni < 4; ni++) {
        int col = n0 + wn * 32 + ni * 8 + qc;
        bv0[ni] = bias[col];
        bv1[ni] = bias[col + 1];
    }
#pragma unroll
    for (int mi = 0; mi < 4; mi++) {
        int r = m0 + wm * 64 + mi * 16 + qr;
#pragma unroll
        for (int ni = 0; ni < 4; ni++) {
            int col = n0 + wn * 32 + ni * 8 + qc;
            if (r < NN) {
                float2 v = make_float2(c[mi][ni][0] + bv0[ni], c[mi][ni][1] + bv1[ni]);
                *(float2*)&C[(size_t)r * cout + col] = v;
            }
            if (r + 8 < NN) {
                float2 v = make_float2(c[mi][ni][2] + bv0[ni], c[mi][ni][3] + bv1[ni]);
                *(float2*)&C[(size_t)(r + 8) * cout + col] = v;
            }
        }
    }
}

// ---------------- GraphNorm + leaky relu, in-place (two-pass) ----------------
__global__ void k_graphnorm(float* __restrict__ X, const float* __restrict__ w,
                            const float* __restrict__ b, const float* __restrict__ ms,
                            int cout) {
    int bg = blockIdx.x;
    int c = blockIdx.y * blockDim.x + threadIdx.x;
    if (c >= cout) return;
    int s = g_ptr[bg];
    int e = g_ptr[bg + 1];
    float invc = 1.0f / g_cnt[bg];
    float s1 = 0.0f, s2 = 0.0f;
    for (int n = s; n < e; n++) {
        float v = X[(size_t)n * cout + c];
        s1 += v;
        s2 += v * v;
    }
    float mean = s1 * invc;
    float m = ms[c] * mean;
    float var = fmaxf(s2 * invc - 2.0f * m * mean + m * m, 0.0f);
    float inv = rsqrtf(var + GN_EPS);
    float ww = w[c] * inv;
    float bb = b[c];
    for (int n = s; n < e; n++) {
        float d = X[(size_t)n * cout + c] - m;
        float v = ww * d + bb;
        X[(size_t)n * cout + c] = (v >= 0.f) ? v : 0.2f * v;
    }
}

// ---------------- residual + mean pool ----------------
__global__ void k_pool(const float* __restrict__ h, const float* __restrict__ x) {
    int bg = blockIdx.x;
    int c = threadIdx.x;  // 128
    int s = g_ptr[bg];
    int e = g_ptr[bg + 1];
    float sum = 0.0f;
    for (int n = s; n < e; n++)
        sum += h[(size_t)n * 128 + c] + x[(size_t)n * 128 + c];
    g_pool[bg * 128 + c] = sum / g_cnt[bg];
}

// ---------------- MLP head ----------------
__global__ void k_head(const float* __restrict__ W1, const float* __restrict__ b1,
                       const float* __restrict__ W2, const float* __restrict__ b2,
                       float* __restrict__ out) {
    int bg = blockIdx.x;
    __shared__ float hid[64];
    int j = threadIdx.x;  // 64
    float s = b1[j];
    for (int i = 0; i < 128; i++) s += g_pool[bg * 128 + i] * W1[i * 64 + j];
    hid[j] = tanhf(s);
    __syncthreads();
    if (j < 10) {
        float o = b2[j];
        for (int i = 0; i < 64; i++) o += hid[i] * W2[i * 10 + j];
        out[bg * 10 + j] = o;
    }
}

// ---------------- host orchestration ----------------
static void launch_prop(const float* h, const float* base, float scale, float beta,
                        float* out, int cin) {
    switch (cin / 128) {
        case 1: k_prop<1><<<NN, 128>>>(h, base, scale, beta, out, cin); break;
        case 2: k_prop<2><<<NN, 128>>>(h, base, scale, beta, out, cin); break;
        default: k_prop<4><<<NN, 128>>>(h, base, scale, beta, out, cin); break;
    }
}

static void run_layer(const float* h, float* out, float* tx1, float* tx2,
                      int cin, int cout, void* const* d_in, int base_idx) {
    launch_prop(h, nullptr, 1.0f, 0.0f, tx1, cin);
    launch_prop(tx1, h, 2.0f, -1.0f, tx2, cin);
    k_convA<<<cdiv(NN * cin, 256), 256>>>(h, tx1, tx2, cin);
    k_convW<<<cdiv(cout * 9 * cin, 256), 256>>>((const float*)d_in[base_idx], cin, cout);
    dim3 gg(MPAD / 128, cout / 128);
    k_gemm_mma<<<gg, 256>>>((const float*)d_in[base_idx + 1], out, cin, cout);
    dim3 gn(BB, cdiv(cout, 128));
    k_graphnorm<<<gn, 128>>>(out,
                             (const float*)d_in[base_idx + 2],
                             (const float*)d_in[base_idx + 3],
                             (const float*)d_in[base_idx + 4], cout);
}

extern "C" void kernel_launch(void* const* d_in, const int* in_sizes, int n_in,
                              void* d_out, int out_size) {
    const float* x = (const float*)d_in[0];
    const int* ei = (const int*)d_in[1];
    const int* src = ei;
    const int* dst = ei + EE;
    const int* batch = (const int*)d_in[2];

    float *f0, *f1, *tx1, *tx2;
    cudaGetSymbolAddress((void**)&f0, g_f0);
    cudaGetSymbolAddress((void**)&f1, g_f1);
    cudaGetSymbolAddress((void**)&tx1, g_tx1);
    cudaGetSymbolAddress((void**)&tx2, g_tx2);

    // ---- setup: degrees, CSR, graph segments ----
    k_zero_deg<<<cdiv(NN, 256), 256>>>();
    k_deg<<<cdiv(EE, 256), 256>>>(dst);
    k_dinv<<<cdiv(NN, 256), 256>>>();
    k_scan<<<1, 1024>>>();
    k_fill<<<cdiv(EE, 256), 256>>>(src, dst);
    k_ptr<<<cdiv(NN, 256), 256>>>(batch);
    k_cnt<<<1, 64>>>();

    // ---- 4 Cheb layers ----
    run_layer(x,  f0, tx1, tx2, 128, 256, d_in, 3);
    run_layer(f0, f1, tx1, tx2, 256, 512, d_in, 8);
    run_layer(f1, f0, tx1, tx2, 512, 256, d_in, 13);
    run_layer(f0, f1, tx1, tx2, 256, 128, d_in, 18);

    // ---- residual + pool + head ----
    k_pool<<<BB, 128>>>(f1, x);
    k_head<<<BB, 64>>>((const float*)d_in[23], (const float*)d_in[24],
                       (const float*)d_in[25], (const float*)d_in[26],
                       (float*)d_out);
}